// round 2
// baseline (speedup 1.0000x reference)
#include <cuda_runtime.h>
#include <cuda_bf16.h>

// Batched Bloch RK4. RHS is affine per batch element:
//   u' = -g u ;  [v w]' = [[-g,-Om],[Om,-2g]][v w] + [0,-2g]
// RK4 with step h on an affine system y'=Ay+b is EXACTLY
//   y+ = M y + c,  M = I + Bm + Bm^2/2 + Bm^3/6 + Bm^4/24   (Bm = h*A)
//   c  = (hI + h^2 A/2 + h^3 A^2/6 + h^4 A^3/24) b
// Vectorized 4 batch elements/thread so per-step output (48 B) is 3x STG.128.
// Propagators cached in a 2-slot LRU keyed on the fp32 dt value (dt of
// arange(T)*0.01f alternates between adjacent representables).

#ifndef TMAX
#define TMAX 4096
#endif

__device__ __forceinline__ void make_prop(
    float h, const float Om[4], const float g[4],
    float pu[4], float m00[4], float m01[4], float m10[4], float m11[4],
    float c0[4], float c1[4])
{
    const float i6 = 1.f / 6.f, i24 = 1.f / 24.f;
#pragma unroll
    for (int j = 0; j < 4; ++j) {
        float b00 = -g[j] * h, b01 = -Om[j] * h, b10 = Om[j] * h, b11 = -2.f * g[j] * h;
        float s00 = b00 * b00 + b01 * b10;
        float s01 = b00 * b01 + b01 * b11;
        float s10 = b10 * b00 + b11 * b10;
        float s11 = b10 * b01 + b11 * b11;
        float t00 = s00 * b00 + s01 * b10;
        float t01 = s00 * b01 + s01 * b11;
        float t10 = s10 * b00 + s11 * b10;
        float t11 = s10 * b01 + s11 * b11;
        float q00 = s00 * s00 + s01 * s10;
        float q01 = s00 * s01 + s01 * s11;
        float q10 = s10 * s00 + s11 * s10;
        float q11 = s10 * s01 + s11 * s11;
        m00[j] = 1.f + b00 + 0.5f * s00 + i6 * t00 + i24 * q00;
        m01[j] =       b01 + 0.5f * s01 + i6 * t01 + i24 * q01;
        m10[j] =       b10 + 0.5f * s10 + i6 * t10 + i24 * q10;
        m11[j] = 1.f + b11 + 0.5f * s11 + i6 * t11 + i24 * q11;
        float p01 = h * (0.5f * b01 + i6 * s01 + i24 * t01);
        float p11 = h * (1.f + 0.5f * b11 + i6 * s11 + i24 * t11);
        float nb = -2.f * g[j];
        c0[j] = p01 * nb;
        c1[j] = p11 * nb;
        float be = -g[j] * h;
        pu[j] = 1.f + be * (1.f + be * (0.5f + be * (i6 + be * i24)));
    }
}

#define APPLY(pu, m00, m01, m10, m11, c0, c1)                               \
    _Pragma("unroll")                                                       \
    for (int j = 0; j < 4; ++j) {                                           \
        u[j] = pu[j] * u[j];                                                \
        float vn = fmaf(m00[j], v[j], fmaf(m01[j], w[j], c0[j]));           \
        float wn = fmaf(m10[j], v[j], fmaf(m11[j], w[j], c1[j]));           \
        v[j] = vn; w[j] = wn;                                               \
    }

__global__ __launch_bounds__(32) void bloch_rk4_vec4(
    const float* __restrict__ y0,
    const float* __restrict__ ts,
    const float* __restrict__ params,
    float* __restrict__ out,
    int B, int T)
{
    __shared__ float s_ts[TMAX];
    int tcap = (T < TMAX) ? T : TMAX;
    for (int i = threadIdx.x; i < tcap; i += blockDim.x) s_ts[i] = ts[i];
    __syncthreads();

    int tid = blockIdx.x * blockDim.x + threadIdx.x;
    long long base = 4LL * tid;            // first of 4 batch elements
    if (base >= B) return;

    // ---- load 4 elements' state + params (12 contiguous floats each) ----
    float u[4], v[4], w[4], Om[4], g[4];
    const float4* y4 = (const float4*)(y0 + base * 3);
    const float4* p4 = (const float4*)(params + base * 3);
    float4 a0 = y4[0], a1 = y4[1], a2 = y4[2];
    u[0] = a0.x; v[0] = a0.y; w[0] = a0.z;
    u[1] = a0.w; v[1] = a1.x; w[1] = a1.y;
    u[2] = a1.z; v[2] = a1.w; w[2] = a2.x;
    u[3] = a2.y; v[3] = a2.z; w[3] = a2.w;
    float4 q0 = p4[0], q1 = p4[1], q2 = p4[2];
    Om[0] = q0.x; g[0] = q0.z;
    Om[1] = q0.w; g[1] = q1.y;
    Om[2] = q1.z; g[2] = q2.x;
    Om[3] = q2.y; g[3] = q2.w;

    float4* o = (float4*)(out + base * 3);
    const long long strideF4 = (3LL * B) / 4;   // float4s per timestep row

    // ---- t = 0 row ----
    __stcs(o + 0, make_float4(u[0], v[0], w[0], u[1]));
    __stcs(o + 1, make_float4(v[1], w[1], u[2], v[2]));
    __stcs(o + 2, make_float4(w[2], u[3], v[3], w[3]));

    // ---- 2-slot LRU propagator cache ----
    float Apu[4], Am00[4], Am01[4], Am10[4], Am11[4], Ac0[4], Ac1[4];
    float Bpu[4], Bm00[4], Bm01[4], Bm10[4], Bm11[4], Bc0[4], Bc1[4];
    float hA = __int_as_float(0x7fc00000);   // NaN -> never matches
    float hB = __int_as_float(0x7fc00000);
    bool lastA = false;                      // most-recently-used slot
    float ts_prev = (tcap > 0) ? s_ts[0] : 0.f;

    for (int t = 1; t < T; ++t) {
        float ts_cur = (t < TMAX) ? s_ts[t] : __ldg(ts + t);
        float h = ts_cur - ts_prev;
        ts_prev = ts_cur;

        if (h == hA) {                                   // warp-uniform
            APPLY(Apu, Am00, Am01, Am10, Am11, Ac0, Ac1);
            lastA = true;
        } else if (h == hB) {
            APPLY(Bpu, Bm00, Bm01, Bm10, Bm11, Bc0, Bc1);
            lastA = false;
        } else if (!lastA) {                             // evict LRU = A
            make_prop(h, Om, g, Apu, Am00, Am01, Am10, Am11, Ac0, Ac1);
            hA = h;
            APPLY(Apu, Am00, Am01, Am10, Am11, Ac0, Ac1);
            lastA = true;
        } else {                                         // evict LRU = B
            make_prop(h, Om, g, Bpu, Bm00, Bm01, Bm10, Bm11, Bc0, Bc1);
            hB = h;
            APPLY(Bpu, Bm00, Bm01, Bm10, Bm11, Bc0, Bc1);
            lastA = false;
        }

        o += strideF4;
        __stcs(o + 0, make_float4(u[0], v[0], w[0], u[1]));
        __stcs(o + 1, make_float4(v[1], w[1], u[2], v[2]));
        __stcs(o + 2, make_float4(w[2], u[3], v[3], w[3]));
    }
}

// ---- scalar fallback (B not divisible by 4) ----
__global__ __launch_bounds__(256) void bloch_rk4_scalar(
    const float* __restrict__ y0,
    const float* __restrict__ ts,
    const float* __restrict__ params,
    float* __restrict__ out,
    int B, int T)
{
    __shared__ float s_ts[TMAX];
    int tcap = (T < TMAX) ? T : TMAX;
    for (int i = threadIdx.x; i < tcap; i += blockDim.x) s_ts[i] = ts[i];
    __syncthreads();

    int b = blockIdx.x * blockDim.x + threadIdx.x;
    if (b >= B) return;

    float u = y0[3 * b + 0], v = y0[3 * b + 1], w = y0[3 * b + 2];
    float Omv = params[3 * b + 0];
    float gv  = params[3 * b + 2];

    const long long B3 = 3LL * B;
    float* o = out + 3LL * b;
    o[0] = u; o[1] = v; o[2] = w;

    float Om1[4] = {Omv, Omv, Omv, Omv}, g1[4] = {gv, gv, gv, gv};
    float pu[4], m00[4], m01[4], m10[4], m11[4], c0[4], c1[4];
    float prev_h = __int_as_float(0x7fc00000);
    float ts_prev = (tcap > 0) ? s_ts[0] : 0.f;

    for (int t = 1; t < T; ++t) {
        float ts_cur = (t < TMAX) ? s_ts[t] : __ldg(ts + t);
        float h = ts_cur - ts_prev;
        ts_prev = ts_cur;
        if (h != prev_h) {
            prev_h = h;
            make_prop(h, Om1, g1, pu, m00, m01, m10, m11, c0, c1);
        }
        u = pu[0] * u;
        float vn = fmaf(m00[0], v, fmaf(m01[0], w, c0[0]));
        float wn = fmaf(m10[0], v, fmaf(m11[0], w, c1[0]));
        v = vn; w = wn;
        o += B3;
        o[0] = u; o[1] = v; o[2] = w;
    }
}

extern "C" void kernel_launch(void* const* d_in, const int* in_sizes, int n_in,
                              void* d_out, int out_size) {
    const float* y0     = (const float*)d_in[0];   // (B,3)
    const float* ts     = (const float*)d_in[1];   // (T,)
    const float* params = (const float*)d_in[2];   // (B,3)
    float* out = (float*)d_out;                    // (T,B,3)

    int B = in_sizes[0] / 3;
    int T = in_sizes[1];

    if ((B & 3) == 0) {
        int nthreads = B / 4;
        int tpb = 32;
        int blocks = (nthreads + tpb - 1) / tpb;
        bloch_rk4_vec4<<<blocks, tpb>>>(y0, ts, params, out, B, T);
    } else {
        int tpb = 256;
        int blocks = (B + tpb - 1) / tpb;
        bloch_rk4_scalar<<<blocks, tpb>>>(y0, ts, params, out, B, T);
    }
}